// round 7
// baseline (speedup 1.0000x reference)
#include <cuda_runtime.h>

// ---------------- constants ----------------
#define C_NUM   80
#define TOPK_N  1000
#define CONF_T  0.05f
#define NMS_THR 0.6f
#define IMG_INV (1.0f/2048.0f)
#define HBINS   16384
#define CAND_CAP 65536
#define N_ALL   3000
#define ROWS0   196608
#define ROWS1   49152
#define ROWS2   12288
#define RTOT    258048
#define GRID_R  81          // 3 (levels) * 27 select slots; 80 classes + 1 spare
#define TPB_R   256
#define CHUNK   2048

// ---------------- device scratch ----------------
__device__ float              g_b[RTOT];
__device__ unsigned int       g_hist[3 * HBINS];
__device__ unsigned int       g_cnt[3];
__device__ unsigned int       g_Tbin[3];
__device__ unsigned long long g_cand[3][CAND_CAP];
__device__ unsigned long long g_topk[3][TOPK_N];
__device__ unsigned int       g_bar[3];

__device__ __forceinline__ float sigm(float x) { return 1.0f / (1.0f + expf(-x)); }

__device__ __forceinline__ void level_of(int grow, int& lvl, int& r) {
    if (grow < ROWS0)              { lvl = 0; r = grow; }
    else if (grow < ROWS0 + ROWS1) { lvl = 1; r = grow - ROWS0; }
    else                           { lvl = 2; r = grow - ROWS0 - ROWS1; }
}

__device__ __forceinline__ void gbar(unsigned int* c, unsigned int tgt) {
    __syncthreads();
    if (threadIdx.x == 0) {
        __threadfence();
        atomicAdd(c, 1u);
        while (*(volatile unsigned int*)c < tgt) __nanosleep(32);
        __threadfence();
    }
    __syncthreads();
}

// ============ K1: per-anchor bound + histogram (4 threads/row) ============
__global__ void k_rowmax(const float* __restrict__ obj0, const float* __restrict__ cls0,
                         const float* __restrict__ obj1, const float* __restrict__ cls1,
                         const float* __restrict__ obj2, const float* __restrict__ cls2) {
    if (blockIdx.x == 0 && threadIdx.x < 3) g_bar[threadIdx.x] = 0u;  // reset k_rest barriers
    int g = blockIdx.x * blockDim.x + threadIdx.x;
    int grow = g >> 2;
    int sub = g & 3;
    if (grow >= RTOT) return;
    int lvl, r;
    level_of(grow, lvl, r);
    const float* cls = (lvl == 0) ? cls0 : ((lvl == 1) ? cls1 : cls2);
    const float4* c4 = reinterpret_cast<const float4*>(cls) + (size_t)r * 20;
    float mx = -1e30f;
#pragma unroll
    for (int it = 0; it < 5; it++) {
        float4 v = c4[it * 4 + sub];
        mx = fmaxf(mx, fmaxf(fmaxf(v.x, v.y), fmaxf(v.z, v.w)));
    }
    mx = fmaxf(mx, __shfl_xor_sync(0xFFFFFFFFu, mx, 1));
    mx = fmaxf(mx, __shfl_xor_sync(0xFFFFFFFFu, mx, 2));
    if (sub == 0) {
        const float* obj = (lvl == 0) ? obj0 : ((lvl == 1) ? obj1 : obj2);
        float b = sqrtf(sigm(obj[r]) * sigm(mx));
        g_b[grow] = b;
        int bin = (int)(b * (float)HBINS);
        if (bin > HBINS - 1) bin = HBINS - 1;
        atomicAdd(&g_hist[lvl * HBINS + bin], 1u);
    }
}

// ============ K2: findT -> compact -> rank-select -> per-class NMS ============
extern __shared__ unsigned char dynb[];

__global__ __launch_bounds__(TPB_R, 1)
void k_rest(const float* __restrict__ obj0, const float* __restrict__ cls0,
            const float* __restrict__ obj1, const float* __restrict__ cls1,
            const float* __restrict__ obj2, const float* __restrict__ cls2,
            const float* __restrict__ r0, const float* __restrict__ r1,
            const float* __restrict__ r2, const float* __restrict__ anc,
            float* __restrict__ out) {
    int tid = threadIdx.x;
    int bid = blockIdx.x;

    // ---- phase F: per-level threshold (blocks 0..2) ----
    if (bid < 3) {
        __shared__ unsigned int csum[256];
        __shared__ unsigned int cbins[64];
        __shared__ int s_ch;
        __shared__ unsigned int s_cum;
        int lvl = bid;
        unsigned int s = 0;
        int base = lvl * HBINS + tid * 64;
#pragma unroll 8
        for (int i = 0; i < 64; i++) s += g_hist[base + i];
        csum[tid] = s;
        __syncthreads();
        if (tid == 0) {
            unsigned int cum = 0;
            int ch = 255;
            for (; ch > 0; ch--) {
                if (cum + csum[ch] >= TOPK_N) break;
                cum += csum[ch];
            }
            s_ch = ch; s_cum = cum;
        }
        __syncthreads();
        int ch = s_ch;
        if (tid < 64) cbins[tid] = g_hist[lvl * HBINS + ch * 64 + tid];
        __syncthreads();
        if (tid == 0) {
            unsigned int cum = s_cum;
            int bin = 63;
            for (; bin > 0; bin--) {
                cum += cbins[bin];
                if (cum >= TOPK_N) break;
            }
            g_Tbin[lvl] = (unsigned int)(ch * 64 + bin);
            g_cnt[lvl] = 0u;
        }
    }

    gbar(&g_bar[0], GRID_R);

    // ---- phase C: sparse expansion (grid-stride over rows) ----
    {
        __shared__ unsigned int sT[3];
        if (tid < 3) sT[tid] = *(volatile unsigned int*)&g_Tbin[tid];
        __syncthreads();
        for (int grow = bid * TPB_R + tid; grow < RTOT; grow += GRID_R * TPB_R) {
            int lvl, r;
            level_of(grow, lvl, r);
            int B = (int)sT[lvl];
            if ((int)(g_b[grow] * (float)HBINS) < B) continue;  // same discretization as K1
            const float* obj = (lvl == 0) ? obj0 : ((lvl == 1) ? obj1 : obj2);
            const float* cls = (lvl == 0) ? cls0 : ((lvl == 1) ? cls1 : cls2);
            float so = sigm(obj[r]);
            const float4* c4 = reinterpret_cast<const float4*>(cls) + (size_t)r * 20;
            float4 vbuf[20];
#pragma unroll
            for (int j = 0; j < 20; j++) vbuf[j] = c4[j];
#pragma unroll
            for (int j = 0; j < 20; j++) {
                float vv[4] = {vbuf[j].x, vbuf[j].y, vbuf[j].z, vbuf[j].w};
#pragma unroll
                for (int k = 0; k < 4; k++) {
                    float s = sqrtf(so * sigm(vv[k]));
                    if ((int)(s * (float)HBINS) >= B) {
                        unsigned int p = atomicAdd(&g_cnt[lvl], 1u);
                        if (p < CAND_CAP) {
                            int idx = r * C_NUM + j * 4 + k;
                            g_cand[lvl][p] =
                                ((unsigned long long)__float_as_uint(s) << 24) |
                                (unsigned long long)(0xFFFFFF - idx);
                        }
                    }
                }
            }
        }
    }

    gbar(&g_bar[1], GRID_R);

    // ---- phase S: exact rank select; g_topk lands sorted ----
    {
        unsigned long long* ch = (unsigned long long*)dynb;  // CHUNK keys
        int lvl = bid % 3;
        int bslot = bid / 3;                                  // 0..26
        unsigned int cnt = *(volatile unsigned int*)&g_cnt[lvl];
        if (cnt > CAND_CAP) cnt = CAND_CAP;
        const unsigned long long* cand = g_cand[lvl];
        for (int ibase = bslot * TPB_R; ibase < (int)cnt; ibase += 27 * TPB_R) {
            int i = ibase + tid;
            unsigned long long ki = (i < (int)cnt) ? cand[i] : 0xFFFFFFFFFFFFFFFFULL;
            int rank = 0;
            for (int cb = 0; cb < (int)cnt; cb += CHUNK) {
                int m = min(CHUNK, (int)cnt - cb);
                __syncthreads();
                for (int j = tid; j < CHUNK; j += TPB_R)
                    ch[j] = (j < m) ? cand[cb + j] : 0ULL;    // 0 never > any real key
                __syncthreads();
#pragma unroll 8
                for (int j = 0; j < CHUNK; j++)
                    rank += (ch[j] > ki);
            }
            if (i < (int)cnt && rank < TOPK_N) g_topk[lvl][rank] = ki;
        }
    }

    gbar(&g_bar[2], GRID_R);

    // ---- phase N: per-class decode + merge-rank + NMS (blocks 0..79) ----
    // zero histogram for the next graph replay
    for (int i = bid * TPB_R + tid; i < 3 * HBINS; i += GRID_R * TPB_R) g_hist[i] = 0u;
    if (bid >= C_NUM) return;
    {
        int c = bid;
        unsigned long long* gk  = (unsigned long long*)dynb;            // 3000*8 = 24000
        unsigned char* lab      = (unsigned char*)(dynb + 24000);       // 3000
        unsigned long long* lg  = (unsigned long long*)(dynb + 27008);  // 1024*8
        unsigned long long* lg2 = (unsigned long long*)(dynb + 35200);  // 1024*8
        float4* lbox            = (float4*)(dynb + 43392);              // 1024*16
        float*  lare            = (float*)(dynb + 59776);               // 1024*4
        int*    lrnk            = (int*)(dynb + 63872);                 // 1024*4
        unsigned char* lsup     = (unsigned char*)(dynb + 67968);       // 1024
        __shared__ unsigned int s_n;
        __shared__ float s_anc[18];
        if (tid == 0) s_n = 0u;
        if (tid < 18) s_anc[tid] = anc[tid];

        for (int i = tid; i < N_ALL; i += TPB_R) {
            int lvl = i / TOPK_N;
            unsigned long long key = g_topk[lvl][i - lvl * TOPK_N];
            unsigned int sb = (unsigned int)(key >> 24);
            float s = __uint_as_float(sb);
            unsigned int zs = (s > CONF_T) ? sb : 0u;
            gk[i] = ((unsigned long long)zs << 12) | (unsigned long long)(4095 - i);
            int idx = 0xFFFFFF - (int)(key & 0xFFFFFFULL);
            lab[i] = (unsigned char)(idx % C_NUM);
        }
        __syncthreads();

        for (int i = tid; i < N_ALL; i += TPB_R) {
            if (lab[i] == (unsigned char)c) {
                unsigned int p = atomicAdd(&s_n, 1u);
                if (p < 1024u) lg[p] = gk[i];
            }
        }
        __syncthreads();
        int n = (int)min(s_n, 1024u);
        // order class subset desc by counting rank (exact, unique keys)
        for (int j = tid; j < n; j += TPB_R) {
            unsigned long long kj = lg[j];
            int r = 0;
            for (int k = 0; k < n; k++) r += (lg[k] > kj);
            lg2[r] = kj;
        }
        __syncthreads();

        float offv = (float)c * 100000.0f;
        for (int j = tid; j < n; j += TPB_R) {
            unsigned long long gkv = lg2[j];
            int i = 4095 - (int)(gkv & 0xFFFULL);
            int lvl = i / TOPK_N;
            int r = i - lvl * TOPK_N;
            unsigned long long key = g_topk[lvl][r];
            int rank = r;
#pragma unroll
            for (int l = 0; l < 3; l++) {
                if (l == lvl) continue;
                const unsigned long long* arr = gk + l * TOPK_N;
                int lo = 0, hi = TOPK_N;
                while (lo < hi) {
                    int mid = (lo + hi) >> 1;
                    if (arr[mid] > gkv) lo = mid + 1; else hi = mid;
                }
                rank += lo;
            }
            int idx = 0xFFFFFF - (int)(key & 0xFFFFFFULL);
            int m = idx / C_NUM;
            int a = m % 3;
            int cell = m / 3;
            int W = (lvl == 0) ? 256 : ((lvl == 1) ? 128 : 64);
            float stride = (lvl == 0) ? 8.0f : ((lvl == 1) ? 16.0f : 32.0f);
            int x = cell % W, y = cell / W;
            const float* reg = ((lvl == 0) ? r0 : ((lvl == 1) ? r1 : r2)) + (size_t)m * 4;
            float cx = ((float)x + 0.5f) * stride + (sigm(reg[0]) * 3.0f - 1.5f) * stride;
            float cy = ((float)y + 0.5f) * stride + (sigm(reg[1]) * 3.0f - 1.5f) * stride;
            float bw = expf(reg[2]) * s_anc[lvl * 6 + a * 2 + 0];
            float bh = expf(reg[3]) * s_anc[lvl * 6 + a * 2 + 1];
            float4 b;
            b.x = cx - 0.5f * bw; b.y = cy - 0.5f * bh;
            b.z = cx + 0.5f * bw; b.w = cy + 0.5f * bh;
            out[rank * 4 + 0] = fminf(fmaxf(b.x * IMG_INV, 0.0f), 1.0f);
            out[rank * 4 + 1] = fminf(fmaxf(b.y * IMG_INV, 0.0f), 1.0f);
            out[rank * 4 + 2] = fminf(fmaxf(b.z * IMG_INV, 0.0f), 1.0f);
            out[rank * 4 + 3] = fminf(fmaxf(b.w * IMG_INV, 0.0f), 1.0f);
            out[12000 + rank] = 0.0f;
            out[15000 + rank] = (float)c;
            float4 ob;  // reference's offset-quantized boxes (f32 + label*1e5)
            ob.x = b.x + offv; ob.y = b.y + offv; ob.z = b.z + offv; ob.w = b.w + offv;
            lbox[j] = ob;
            lare[j] = (ob.z - ob.x) * (ob.w - ob.y);
            lrnk[j] = rank;
            lsup[j] = 0;
        }
        __syncthreads();

        for (int a = 0; a < n; a++) {
            float sa = __uint_as_float((unsigned int)(lg2[a] >> 12));
            bool keep = (!lsup[a]) && (sa > CONF_T);
            if (keep) {
                if (tid == 0) out[12000 + lrnk[a]] = sa;
                float4 A = lbox[a];
                float arA = lare[a];
                for (int b = a + 1 + tid; b < n; b += TPB_R) {
                    if (lsup[b]) continue;
                    float4 B = lbox[b];
                    float ltx = fmaxf(A.x, B.x), lty = fmaxf(A.y, B.y);
                    float rbx = fminf(A.z, B.z), rby = fminf(A.w, B.w);
                    float wx = fmaxf(rbx - ltx, 0.0f), wy = fmaxf(rby - lty, 0.0f);
                    float inter = wx * wy;
                    float iou = inter / (arA + lare[b] - inter + 1e-12f);
                    if (iou > NMS_THR) lsup[b] = 1;
                }
            }
            __syncthreads();
        }
    }
}

// ---------------- launcher ----------------
extern "C" void kernel_launch(void* const* d_in, const int* in_sizes, int n_in,
                              void* d_out, int out_size) {
    (void)in_sizes; (void)n_in; (void)out_size;
    const float* obj0 = (const float*)d_in[0];
    const float* cls0 = (const float*)d_in[1];
    const float* reg0 = (const float*)d_in[2];
    const float* obj1 = (const float*)d_in[3];
    const float* cls1 = (const float*)d_in[4];
    const float* reg1 = (const float*)d_in[5];
    const float* obj2 = (const float*)d_in[6];
    const float* cls2 = (const float*)d_in[7];
    const float* reg2 = (const float*)d_in[8];
    const float* anc  = (const float*)d_in[9];
    float* out = (float*)d_out;

    const int DYNB = 68992;
    cudaFuncSetAttribute(k_rest, cudaFuncAttributeMaxDynamicSharedMemorySize, DYNB);

    k_rowmax<<<(RTOT * 4 + 255) / 256, 256>>>(obj0, cls0, obj1, cls1, obj2, cls2);
    k_rest<<<GRID_R, TPB_R, DYNB>>>(obj0, cls0, obj1, cls1, obj2, cls2,
                                    reg0, reg1, reg2, anc, out);
}

// round 8
// speedup vs baseline: 1.2970x; 1.2970x over previous
#include <cuda_runtime.h>

// ---------------- constants ----------------
#define C_NUM   80
#define TOPK_N  1000
#define CONF_T  0.05f
#define NMS_THR 0.6f
#define IMG_INV (1.0f/2048.0f)
#define HBINS   16384
#define CAND_CAP 65536
#define N_ALL   3000
#define ROWS0   196608
#define ROWS1   49152
#define ROWS2   12288
#define RTOT    258048
#define TPB_S   512
#define GRID_S  80
#define GATHER_CAP 2048

// ---------------- device scratch ----------------
__device__ float              g_b[RTOT];
__device__ unsigned int       g_hist[3 * HBINS];   // row-bound histogram
__device__ unsigned int       g_hist2[3 * HBINS];  // candidate-score histogram
__device__ unsigned int       g_cnt[3];
__device__ unsigned int       g_Tbin[3];
__device__ unsigned long long g_cand[3][CAND_CAP];
__device__ unsigned long long g_topk[3][TOPK_N];
__device__ unsigned int       g_bar0;

__device__ __forceinline__ float sigm(float x) { return 1.0f / (1.0f + expf(-x)); }

__device__ __forceinline__ void level_of(int grow, int& lvl, int& r) {
    if (grow < ROWS0)              { lvl = 0; r = grow; }
    else if (grow < ROWS0 + ROWS1) { lvl = 1; r = grow - ROWS0; }
    else                           { lvl = 2; r = grow - ROWS0 - ROWS1; }
}

__device__ __forceinline__ void gbar(unsigned int* c, unsigned int tgt) {
    __syncthreads();
    if (threadIdx.x == 0) {
        __threadfence();
        atomicAdd(c, 1u);
        while (*(volatile unsigned int*)c < tgt) __nanosleep(32);
        __threadfence();
    }
    __syncthreads();
}

// ============ K1: per-anchor bound + histogram (4 threads/row) ============
__global__ void k_rowmax(const float* __restrict__ obj0, const float* __restrict__ cls0,
                         const float* __restrict__ obj1, const float* __restrict__ cls1,
                         const float* __restrict__ obj2, const float* __restrict__ cls2) {
    if (blockIdx.x == 0 && threadIdx.x == 0) g_bar0 = 0u;  // reset k_select_nms barrier
    int g = blockIdx.x * blockDim.x + threadIdx.x;
    int grow = g >> 2;
    int sub = g & 3;
    if (grow >= RTOT) return;
    int lvl, r;
    level_of(grow, lvl, r);
    const float* cls = (lvl == 0) ? cls0 : ((lvl == 1) ? cls1 : cls2);
    const float4* c4 = reinterpret_cast<const float4*>(cls) + (size_t)r * 20;
    float mx = -1e30f;
#pragma unroll
    for (int it = 0; it < 5; it++) {
        float4 v = c4[it * 4 + sub];
        mx = fmaxf(mx, fmaxf(fmaxf(v.x, v.y), fmaxf(v.z, v.w)));
    }
    mx = fmaxf(mx, __shfl_xor_sync(0xFFFFFFFFu, mx, 1));
    mx = fmaxf(mx, __shfl_xor_sync(0xFFFFFFFFu, mx, 2));
    if (sub == 0) {
        const float* obj = (lvl == 0) ? obj0 : ((lvl == 1) ? obj1 : obj2);
        float b = sqrtf(sigm(obj[r]) * sigm(mx));
        g_b[grow] = b;
        int bin = (int)(b * (float)HBINS);
        if (bin > HBINS - 1) bin = HBINS - 1;
        atomicAdd(&g_hist[lvl * HBINS + bin], 1u);
    }
}

// ============ K2: per-level row-bound threshold (3 blocks) ============
__global__ void k_findT() {
    int lvl = blockIdx.x;
    __shared__ unsigned int csum[256];
    __shared__ unsigned int cbins[64];
    __shared__ int s_ch;
    __shared__ unsigned int s_cum;
    unsigned int s = 0;
    int base = lvl * HBINS + threadIdx.x * 64;
#pragma unroll 8
    for (int i = 0; i < 64; i++) s += g_hist[base + i];
    csum[threadIdx.x] = s;
    __syncthreads();
    if (threadIdx.x == 0) {
        unsigned int cum = 0;
        int ch = 255;
        for (; ch > 0; ch--) {
            if (cum + csum[ch] >= TOPK_N) break;
            cum += csum[ch];
        }
        s_ch = ch; s_cum = cum;
    }
    __syncthreads();
    int ch = s_ch;
    if (threadIdx.x < 64) cbins[threadIdx.x] = g_hist[lvl * HBINS + ch * 64 + threadIdx.x];
    __syncthreads();
    if (threadIdx.x == 0) {
        unsigned int cum = s_cum;
        int bin = 63;
        for (; bin > 0; bin--) {
            cum += cbins[bin];
            if (cum >= TOPK_N) break;
        }
        g_Tbin[lvl] = (unsigned int)(ch * 64 + bin);
        g_cnt[lvl] = 0u;
    }
}

// ============ K3: sparse expansion + candidate histogram (1 thread/row) ============
__global__ void k_compact(const float* __restrict__ obj0, const float* __restrict__ cls0,
                          const float* __restrict__ obj1, const float* __restrict__ cls1,
                          const float* __restrict__ obj2, const float* __restrict__ cls2) {
    __shared__ unsigned int sT[3];
    if (threadIdx.x < 3) sT[threadIdx.x] = g_Tbin[threadIdx.x];
    __syncthreads();
    int grow = blockIdx.x * blockDim.x + threadIdx.x;
    if (grow >= RTOT) return;
    int lvl, r;
    level_of(grow, lvl, r);
    int B = (int)sT[lvl];
    if ((int)(g_b[grow] * (float)HBINS) < B) return;  // same discretization as K1
    const float* obj = (lvl == 0) ? obj0 : ((lvl == 1) ? obj1 : obj2);
    const float* cls = (lvl == 0) ? cls0 : ((lvl == 1) ? cls1 : cls2);
    float so = sigm(obj[r]);
    const float4* c4 = reinterpret_cast<const float4*>(cls) + (size_t)r * 20;
    float4 vbuf[20];
#pragma unroll
    for (int j = 0; j < 20; j++) vbuf[j] = c4[j];
#pragma unroll
    for (int j = 0; j < 20; j++) {
        float vv[4] = {vbuf[j].x, vbuf[j].y, vbuf[j].z, vbuf[j].w};
#pragma unroll
        for (int k = 0; k < 4; k++) {
            float s = sqrtf(so * sigm(vv[k]));
            if ((int)(s * (float)HBINS) >= B) {
                unsigned int sb = __float_as_uint(s);
                unsigned int p = atomicAdd(&g_cnt[lvl], 1u);
                if (p < CAND_CAP) {
                    int idx = r * C_NUM + j * 4 + k;
                    g_cand[lvl][p] = ((unsigned long long)sb << 24) |
                                     (unsigned long long)(0xFFFFFF - idx);
                    atomicAdd(&g_hist2[lvl * HBINS + (sb >> 16)], 1u);
                }
            }
        }
    }
}

// ============ K4: exact select (blocks 0..2) + per-class NMS (80 blocks) ============
extern __shared__ unsigned char dynb[];

__global__ __launch_bounds__(TPB_S, 1)
void k_select_nms(const float* __restrict__ r0, const float* __restrict__ r1,
                  const float* __restrict__ r2, const float* __restrict__ anc,
                  float* __restrict__ out) {
    int tid = threadIdx.x;
    int bid = blockIdx.x;

    // ---- phase S: exact top-1000 per level (blocks 0..2) ----
    if (bid < 3) {
        int lvl = bid;
        unsigned int cnt = g_cnt[lvl];
        if (cnt > CAND_CAP) cnt = CAND_CAP;
        const unsigned long long* cand = g_cand[lvl];

        // threshold over candidate-score histogram (bin2 = sb >> 16, monotone)
        __shared__ unsigned int csum[256];
        __shared__ unsigned int cbins[64];
        __shared__ int s_ch;
        __shared__ unsigned int s_cum, s_B2, s_m;
        if (tid < 256) {
            unsigned int s = 0;
            int base = lvl * HBINS + tid * 64;
#pragma unroll 8
            for (int i = 0; i < 64; i++) s += g_hist2[base + i];
            csum[tid] = s;
        }
        __syncthreads();
        if (tid == 0) {
            unsigned int cum = 0;
            int ch = 255;
            for (; ch > 0; ch--) {
                if (cum + csum[ch] >= TOPK_N) break;
                cum += csum[ch];
            }
            s_ch = ch; s_cum = cum;
        }
        __syncthreads();
        if (tid < 64) cbins[tid] = g_hist2[lvl * HBINS + s_ch * 64 + tid];
        __syncthreads();
        if (tid == 0) {
            unsigned int cum = s_cum;
            int bin = 63;
            for (; bin > 0; bin--) {
                cum += cbins[bin];
                if (cum >= TOPK_N) break;
            }
            s_B2 = (unsigned int)(s_ch * 64 + bin);
            s_m = 0u;
        }
        __syncthreads();
        unsigned int B2 = s_B2;

        unsigned long long* sk = (unsigned long long*)dynb;  // GATHER_CAP keys
        for (int i = tid; i < (int)cnt; i += TPB_S) {
            unsigned long long k = cand[i];
            if ((unsigned int)(k >> 40) >= B2) {             // k>>40 == sb>>16
                unsigned int p = atomicAdd(&s_m, 1u);
                if (p < GATHER_CAP) sk[p] = k;
            }
        }
        __syncthreads();
        unsigned int m = s_m;
        if (m <= GATHER_CAP) {
            // exact counting-rank of pruned set (contains the true top-1000)
            for (int j = tid; j < (int)m; j += TPB_S) {
                unsigned long long kj = sk[j];
                int rank = 0;
                for (int k2 = 0; k2 < (int)m; k2++) rank += (sk[k2] > kj);
                if (rank < TOPK_N) g_topk[lvl][rank] = kj;
            }
        } else {
            // fallback: rank all candidates via smem chunks (rare)
            for (int ibase = 0; ibase < (int)cnt; ibase += TPB_S) {
                int i = ibase + tid;
                unsigned long long ki = (i < (int)cnt) ? cand[i] : 0xFFFFFFFFFFFFFFFFULL;
                int rank = 0;
                for (int cb = 0; cb < (int)cnt; cb += GATHER_CAP) {
                    int mm = min(GATHER_CAP, (int)cnt - cb);
                    __syncthreads();
                    for (int j = tid; j < GATHER_CAP; j += TPB_S)
                        sk[j] = (j < mm) ? cand[cb + j] : 0ULL;
                    __syncthreads();
#pragma unroll 8
                    for (int j = 0; j < GATHER_CAP; j++) rank += (sk[j] > ki);
                }
                if (i < (int)cnt && rank < TOPK_N) g_topk[lvl][rank] = ki;
            }
        }
    } else {
        // zero row-bound histogram for the next replay (findT already consumed it)
        for (int i = (bid - 3) * TPB_S + tid; i < 3 * HBINS; i += (GRID_S - 3) * TPB_S)
            g_hist[i] = 0u;
    }

    gbar(&g_bar0, GRID_S);

    // zero candidate histogram for next replay (safe after select consumed it)
    for (int i = bid * TPB_S + tid; i < 3 * HBINS; i += GRID_S * TPB_S) g_hist2[i] = 0u;

    // ---- phase N: per-class decode + merge-rank + NMS (blocks 0..79) ----
    {
        int c = bid;
        unsigned long long* gk  = (unsigned long long*)dynb;            // 3000*8 = 24000
        unsigned char* lab      = (unsigned char*)(dynb + 24000);       // 3000 (+pad)
        unsigned long long* lg  = (unsigned long long*)(dynb + 27008);  // 1024*8
        unsigned long long* lg2 = (unsigned long long*)(dynb + 35200);  // 1024*8
        float4* lbox            = (float4*)(dynb + 43392);              // 1024*16
        float*  lare            = (float*)(dynb + 59776);               // 1024*4
        int*    lrnk            = (int*)(dynb + 63872);                 // 1024*4
        unsigned char* lsup     = (unsigned char*)(dynb + 67968);       // 1024
        __shared__ unsigned int s_n;
        __shared__ float s_anc[18];
        if (tid == 0) s_n = 0u;
        if (tid < 18) s_anc[tid] = anc[tid];

        for (int i = tid; i < N_ALL; i += TPB_S) {
            int lvl = i / TOPK_N;
            unsigned long long key = g_topk[lvl][i - lvl * TOPK_N];
            unsigned int sb = (unsigned int)(key >> 24);
            float s = __uint_as_float(sb);
            unsigned int zs = (s > CONF_T) ? sb : 0u;
            gk[i] = ((unsigned long long)zs << 12) | (unsigned long long)(4095 - i);
            int idx = 0xFFFFFF - (int)(key & 0xFFFFFFULL);
            lab[i] = (unsigned char)(idx % C_NUM);
        }
        __syncthreads();

        for (int i = tid; i < N_ALL; i += TPB_S) {
            if (lab[i] == (unsigned char)c) {
                unsigned int p = atomicAdd(&s_n, 1u);
                if (p < 1024u) lg[p] = gk[i];
            }
        }
        __syncthreads();
        int n = (int)min(s_n, 1024u);
        for (int j = tid; j < n; j += TPB_S) {
            unsigned long long kj = lg[j];
            int r = 0;
            for (int k = 0; k < n; k++) r += (lg[k] > kj);
            lg2[r] = kj;
        }
        __syncthreads();

        float offv = (float)c * 100000.0f;
        for (int j = tid; j < n; j += TPB_S) {
            unsigned long long gkv = lg2[j];
            int i = 4095 - (int)(gkv & 0xFFFULL);
            int lvl = i / TOPK_N;
            int r = i - lvl * TOPK_N;
            unsigned long long key = g_topk[lvl][r];
            int rank = r;
#pragma unroll
            for (int l = 0; l < 3; l++) {
                if (l == lvl) continue;
                const unsigned long long* arr = gk + l * TOPK_N;
                int lo = 0, hi = TOPK_N;
                while (lo < hi) {
                    int mid = (lo + hi) >> 1;
                    if (arr[mid] > gkv) lo = mid + 1; else hi = mid;
                }
                rank += lo;
            }
            int idx = 0xFFFFFF - (int)(key & 0xFFFFFFULL);
            int m = idx / C_NUM;
            int a = m % 3;
            int cell = m / 3;
            int W = (lvl == 0) ? 256 : ((lvl == 1) ? 128 : 64);
            float stride = (lvl == 0) ? 8.0f : ((lvl == 1) ? 16.0f : 32.0f);
            int x = cell % W, y = cell / W;
            const float* reg = ((lvl == 0) ? r0 : ((lvl == 1) ? r1 : r2)) + (size_t)m * 4;
            float cx = ((float)x + 0.5f) * stride + (sigm(reg[0]) * 3.0f - 1.5f) * stride;
            float cy = ((float)y + 0.5f) * stride + (sigm(reg[1]) * 3.0f - 1.5f) * stride;
            float bw = expf(reg[2]) * s_anc[lvl * 6 + a * 2 + 0];
            float bh = expf(reg[3]) * s_anc[lvl * 6 + a * 2 + 1];
            float4 b;
            b.x = cx - 0.5f * bw; b.y = cy - 0.5f * bh;
            b.z = cx + 0.5f * bw; b.w = cy + 0.5f * bh;
            out[rank * 4 + 0] = fminf(fmaxf(b.x * IMG_INV, 0.0f), 1.0f);
            out[rank * 4 + 1] = fminf(fmaxf(b.y * IMG_INV, 0.0f), 1.0f);
            out[rank * 4 + 2] = fminf(fmaxf(b.z * IMG_INV, 0.0f), 1.0f);
            out[rank * 4 + 3] = fminf(fmaxf(b.w * IMG_INV, 0.0f), 1.0f);
            out[12000 + rank] = 0.0f;
            out[15000 + rank] = (float)c;
            float4 ob;  // reference's offset-quantized boxes (f32 + label*1e5)
            ob.x = b.x + offv; ob.y = b.y + offv; ob.z = b.z + offv; ob.w = b.w + offv;
            lbox[j] = ob;
            lare[j] = (ob.z - ob.x) * (ob.w - ob.y);
            lrnk[j] = rank;
            lsup[j] = 0;
        }
        __syncthreads();

        for (int a = 0; a < n; a++) {
            float sa = __uint_as_float((unsigned int)(lg2[a] >> 12));
            bool keep = (!lsup[a]) && (sa > CONF_T);
            if (keep) {
                if (tid == 0) out[12000 + lrnk[a]] = sa;
                float4 A = lbox[a];
                float arA = lare[a];
                for (int b = a + 1 + tid; b < n; b += TPB_S) {
                    if (lsup[b]) continue;
                    float4 B = lbox[b];
                    float ltx = fmaxf(A.x, B.x), lty = fmaxf(A.y, B.y);
                    float rbx = fminf(A.z, B.z), rby = fminf(A.w, B.w);
                    float wx = fmaxf(rbx - ltx, 0.0f), wy = fmaxf(rby - lty, 0.0f);
                    float inter = wx * wy;
                    float iou = inter / (arA + lare[b] - inter + 1e-12f);
                    if (iou > NMS_THR) lsup[b] = 1;
                }
            }
            __syncthreads();
        }
    }
}

// ---------------- launcher ----------------
extern "C" void kernel_launch(void* const* d_in, const int* in_sizes, int n_in,
                              void* d_out, int out_size) {
    (void)in_sizes; (void)n_in; (void)out_size;
    const float* obj0 = (const float*)d_in[0];
    const float* cls0 = (const float*)d_in[1];
    const float* reg0 = (const float*)d_in[2];
    const float* obj1 = (const float*)d_in[3];
    const float* cls1 = (const float*)d_in[4];
    const float* reg1 = (const float*)d_in[5];
    const float* obj2 = (const float*)d_in[6];
    const float* cls2 = (const float*)d_in[7];
    const float* reg2 = (const float*)d_in[8];
    const float* anc  = (const float*)d_in[9];
    float* out = (float*)d_out;

    const int DYNB = 68992;
    cudaFuncSetAttribute(k_select_nms, cudaFuncAttributeMaxDynamicSharedMemorySize, DYNB);

    k_rowmax<<<(RTOT * 4 + 255) / 256, 256>>>(obj0, cls0, obj1, cls1, obj2, cls2);
    k_findT<<<3, 256>>>();
    k_compact<<<(RTOT + 255) / 256, 256>>>(obj0, cls0, obj1, cls1, obj2, cls2);
    k_select_nms<<<GRID_S, TPB_S, DYNB>>>(reg0, reg1, reg2, anc, out);
}